// round 12
// baseline (speedup 1.0000x reference)
#include <cuda_runtime.h>
#include <cuda_fp16.h>
#include <cstdint>
#include <math.h>

#define Bsz 8192
#define Hdim 1024
#define G4 4096
#define HG (1024 * 4096)

#define BM 128      // batch rows per CTA
#define BN 128      // permuted z-cols per CTA (= 32 units x 4 gates)
#define BK 64       // K per pipeline chunk (4 k16-steps)
#define NCHUNK (Hdim / BK)   // 16
#define NT 64       // flat k16 steps
#define NSTAGE 3
#define NTH 256

#define STAGE_BYTES 16384    // A only: 128 rows x 64 half = 16KB
#define SMEM_TOTAL (NSTAGE * STAGE_BYTES + 1024)   // +1KB for 1024-alignment

// ---------------- device scratch (allocation-free) ----------------
// g_W: B in MMA fragment layout: uint4 unit per [l][t(64)][pn(256)][lane(32)]
//   unit = { b0(j0), b1(j0), b0(j1), b1(j1) } per PTX m16n8k16 B mapping
__device__ __align__(256) __half g_W[4ull * HG];
__device__ __align__(256) __half g_h0h[Bsz * Hdim];   // fp16 h row-major
__device__ __align__(256) __half g_hah[Bsz * Hdim];
__device__ __align__(256) __half g_hbh[Bsz * Hdim];
__device__ float  g_ca[Bsz * Hdim];
__device__ float  g_cb[Bsz * Hdim];
__device__ float  g_biasp[4 * G4];       // permuted biases per layer
__device__ float  g_wx0p[G4];            // permuted Wx0

// permuted column layout: n' = (u>>2)*16 + (gate>>1)*8 + (u&3)*2 + (gate&1)
__device__ __forceinline__ int np_to_col(int np) {
    int u = ((np >> 4) << 2) | ((np >> 1) & 3);
    int gate = (((np >> 3) & 1) << 1) | (np & 1);
    return gate * 1024 + u;
}
__device__ __forceinline__ uint32_t smem_u32(const void* p) {
    uint32_t a;
    asm("{ .reg .u64 t; cvta.to.shared.u64 t, %1; cvt.u32.u64 %0, t; }" : "=r"(a) : "l"(p));
    return a;
}
__device__ __forceinline__ float sigm(float z) { return 1.0f / (1.0f + __expf(-z)); }
__device__ __forceinline__ float tanha(float x) {
    float r; asm("tanh.approx.f32 %0, %1;" : "=f"(r) : "f"(x)); return r;
}

#define CP16(dst, src) \
    asm volatile("cp.async.cg.shared.global [%0], [%1], 16;" :: "r"(dst), "l"(src) : "memory")
#define CPCOMMIT() asm volatile("cp.async.commit_group;" ::: "memory")
#define CPWAIT(n)  asm volatile("cp.async.wait_group %0;" :: "n"(n) : "memory")

#define LDSM4(r0, r1, r2, r3, a)                                              \
    asm volatile("ldmatrix.sync.aligned.m8n8.x4.shared.b16 {%0,%1,%2,%3}, [%4];" \
                 : "=r"(r0), "=r"(r1), "=r"(r2), "=r"(r3) : "r"(a))

__device__ __forceinline__ void mma16816(float* d, const uint32_t* a,
                                         uint32_t b0, uint32_t b1) {
    asm volatile(
        "mma.sync.aligned.m16n8k16.row.col.f32.f16.f16.f32 "
        "{%0,%1,%2,%3}, {%4,%5,%6,%7}, {%8,%9}, {%0,%1,%2,%3};\n"
        : "+f"(d[0]), "+f"(d[1]), "+f"(d[2]), "+f"(d[3])
        : "r"(a[0]), "r"(a[1]), "r"(a[2]), "r"(a[3]), "r"(b0), "r"(b1));
}

// ---------------- prep kernels ----------------
// Fold Wx+Wh, permute n', emit B fragment layout (proven in R10/R11).
__global__ void wprep_kernel(const float* __restrict__ Wh0,
                             const float* __restrict__ Wx,
                             const float* __restrict__ Wh) {
    int b = blockIdx.x;            // [l(4)][kc(64)][png(16)]
    int png = b & 15;
    int kc  = (b >> 4) & 63;
    int l   = b >> 10;
    __shared__ __half sm[16][264];
    int tid = threadIdx.x;

    for (int i = tid; i < 4096; i += 256) {
        int uu = i & 63;
        int gate = (i >> 6) & 3;
        int k = i >> 8;
        int col = gate * 1024 + png * 64 + uu;
        int row = kc * 16 + k;
        float v;
        if (l == 0) {
            v = Wh0[(size_t)row * 4096 + col];
        } else {
            size_t o = (size_t)(l - 1) * HG + (size_t)row * 4096 + col;
            v = Wx[o] + Wh[o];
        }
        int npl = ((uu >> 2) << 4) | ((gate >> 1) << 3) | ((uu & 3) << 1) | (gate & 1);
        sm[k][npl] = __float2half_rn(v);
    }
    __syncthreads();

    for (int i = tid; i < 512; i += 256) {
        int lane = i & 31;
        int pnl = i >> 5;
        int n0 = pnl * 16 + (lane >> 2);
        int kk = (lane & 3) * 2;
        __half h[8];
        h[0] = sm[kk][n0];         h[1] = sm[kk + 1][n0];
        h[2] = sm[kk + 8][n0];     h[3] = sm[kk + 9][n0];
        h[4] = sm[kk][n0 + 8];     h[5] = sm[kk + 1][n0 + 8];
        h[6] = sm[kk + 8][n0 + 8]; h[7] = sm[kk + 9][n0 + 8];
        size_t pn = (size_t)png * 16 + pnl;
        size_t unit = (((size_t)l * 64 + kc) * 256 + pn) * 32 + lane;
        ((uint4*)g_W)[unit] = *(const uint4*)h;
    }
}
__global__ void hprep_kernel(const float4* __restrict__ h0) {
    size_t i = (size_t)blockIdx.x * blockDim.x + threadIdx.x;  // < Bsz*Hdim/4
    float4 v = h0[i];
    __half2* d = (__half2*)(g_h0h + i * 4);
    d[0] = __floats2half2_rn(v.x, v.y);
    d[1] = __floats2half2_rn(v.z, v.w);
}
__global__ void bprep_kernel(const float* __restrict__ b0,
                             const float* __restrict__ bb,
                             const float* __restrict__ Wx0) {
    int idx = blockIdx.x * blockDim.x + threadIdx.x;   // < 5*4096
    int np = idx & 4095;
    int l = idx >> 12;
    int col = np_to_col(np);
    if (l < 4) {
        g_biasp[idx] = (l == 0) ? b0[col] : bb[(l - 1) * G4 + col];
    } else {
        g_wx0p[np] = Wx0[col];
    }
}

// --- fused LSTM layer: A via cp.async+smem+LDSM (R7), B via distance-2
//     fragment-layout LDG with a 3-deep register ring ---
__global__ void __launch_bounds__(NTH, 2)
lstm_layer_kernel(int layer,
                  const float* __restrict__ xvec,
                  const float* __restrict__ c0ext,
                  float* __restrict__ dout)
{
    const __half *A;
    const float *c_in;
    float *c_out;
    __half *h_out_h;
    float *h_out_f;
    if (layer == 0) {
        A = g_h0h; c_in = c0ext;
        c_out = g_ca; h_out_h = g_hah; h_out_f = nullptr;
    } else if (layer == 1) {
        A = g_hah; c_in = g_ca;
        c_out = g_cb; h_out_h = g_hbh; h_out_f = nullptr;
    } else if (layer == 2) {
        A = g_hbh; c_in = g_cb;
        c_out = g_ca; h_out_h = g_hah; h_out_f = nullptr;
    } else {
        A = g_hah; c_in = g_ca;
        c_out = dout; h_out_h = nullptr; h_out_f = dout + (size_t)Bsz * Hdim;
    }
    const bool is_l0 = (layer == 0);
    const float* biasp = g_biasp + layer * G4;

    extern __shared__ char smem_raw[];
    const uint32_t sb = (smem_u32(smem_raw) + 1023u) & ~1023u;  // 1024-align
    const int tid  = threadIdx.x;
    const int lane = tid & 31;
    const int wid  = tid >> 5;
    const int wm   = wid >> 2;        // 0..1  (64 m rows each)
    const int wn   = wid & 3;         // 0..3  (32 n' cols each)
    const int rowBase = blockIdx.y * BM;
    const int nBase   = blockIdx.x * BN;

    const __half* Abase = A + (size_t)rowBase * Hdim;
    // B frag pointer: unit = ((l*64 + t)*256 + pn)*32 + lane, pn = bx*8 + wn*2 + jp
    const uint4* Bbase = ((const uint4*)g_W) + (size_t)layer * 524288
        + ((size_t)(blockIdx.x * 8 + wn * 2)) * 32 + lane;

    // ---- cp.async chunk loader: A only (4 x 16B per thread) ----
    auto load_chunk = [&](int s, int c) {
        const uint32_t stA = sb + s * STAGE_BYTES;
        #pragma unroll
        for (int q = 0; q < 4; q++) {
            int i = tid + q * 256;       // 0..1023 : 128 rows x 8 units(16B)
            int r = i >> 3, k16 = i & 7;
            uint32_t dst = stA + r * 128 + 16 * (k16 ^ (r & 7));
            const __half* src = Abase + (size_t)r * Hdim + c * BK + k16 * 8;
            CP16(dst, src);
        }
        CPCOMMIT();
    };

    float acc[4][4][4];
    #pragma unroll
    for (int mt = 0; mt < 4; mt++)
        #pragma unroll
        for (int j = 0; j < 4; j++)
            #pragma unroll
            for (int r = 0; r < 4; r++) acc[mt][j][r] = 0.0f;

    // per-lane ldmatrix base-address components (ks=0)
    const int arow = wm * 64 + (lane & 15);              // per mt: +mt*16
    const int ahi  = lane >> 4;                          // 0/1 (k-half unit)
    uint32_t offA[4];
    #pragma unroll
    for (int mt = 0; mt < 4; mt++) {
        int rr = arow + mt * 16;
        offA[mt] = (uint32_t)(rr * 128 + 16 * (ahi ^ (rr & 7)));
    }

    uint32_t af[4][4];        // A frags, rolling per-mt reload
    uint32_t bf[3][4][2];     // B frags, 3-deep ring, prefetch distance 2

    auto loadB = [&](int nb, int t) {
        uint4 v0 = __ldg(Bbase + (size_t)t * 8192);
        uint4 v1 = __ldg(Bbase + (size_t)t * 8192 + 32);
        bf[nb][0][0] = v0.x; bf[nb][0][1] = v0.y;
        bf[nb][1][0] = v0.z; bf[nb][1][1] = v0.w;
        bf[nb][2][0] = v1.x; bf[nb][2][1] = v1.y;
        bf[nb][3][0] = v1.z; bf[nb][3][1] = v1.w;
    };

    // one k16-step: B prefetch (t+2) first (longest latency), then mma groups
    // with rolling A reloads in the tensor shadow.
    auto ksstep = [&](int t, bool pfA,
                      uint32_t pa0, uint32_t pa1, uint32_t pa2, uint32_t pa3) {
        const int cur = t % 3;
        if (t + 2 < NT) loadB((t + 2) % 3, t + 2);
        #pragma unroll
        for (int j = 0; j < 4; j++)
            mma16816(acc[0][j], af[0], bf[cur][j][0], bf[cur][j][1]);
        if (pfA) LDSM4(af[0][0], af[0][1], af[0][2], af[0][3], pa0);
        #pragma unroll
        for (int j = 0; j < 4; j++)
            mma16816(acc[1][j], af[1], bf[cur][j][0], bf[cur][j][1]);
        if (pfA) LDSM4(af[1][0], af[1][1], af[1][2], af[1][3], pa1);
        #pragma unroll
        for (int j = 0; j < 4; j++)
            mma16816(acc[2][j], af[2], bf[cur][j][0], bf[cur][j][1]);
        if (pfA) LDSM4(af[2][0], af[2][1], af[2][2], af[2][3], pa2);
        #pragma unroll
        for (int j = 0; j < 4; j++)
            mma16816(acc[3][j], af[3], bf[cur][j][0], bf[cur][j][1]);
        if (pfA) LDSM4(af[3][0], af[3][1], af[3][2], af[3][3], pa3);
    };

    // prologue: stages 0,1 in flight; B t=0,1 resident; A ks=0 frags loaded
    load_chunk(0, 0);
    load_chunk(1, 1);
    loadB(0, 0);
    loadB(1, 1);
    CPWAIT(1);
    __syncthreads();
    {
        const uint32_t stA = sb;
        #pragma unroll
        for (int mt = 0; mt < 4; mt++)
            LDSM4(af[mt][0], af[mt][1], af[mt][2], af[mt][3], stA + offA[mt]);
    }

    for (int c = 0; c < NCHUNK; c++) {
        const int s = c % NSTAGE;
        const uint32_t stA = sb + s * STAGE_BYTES;
        uint32_t aA[4];
        #pragma unroll
        for (int mt = 0; mt < 4; mt++) aA[mt] = stA + offA[mt];
        const uint32_t nA = sb + ((c + 1) % NSTAGE) * STAGE_BYTES;
        const int t0 = c * 4;

        // ks=0, ks=1: A prefetch next ks (same stage); B auto t+2
        ksstep(t0 + 0, true, aA[0] ^ 32u, aA[1] ^ 32u, aA[2] ^ 32u, aA[3] ^ 32u);
        ksstep(t0 + 1, true, aA[0] ^ 64u, aA[1] ^ 64u, aA[2] ^ 64u, aA[3] ^ 64u);

        // mid-chunk sync: A group(c+1) complete for everyone; stage (c+2)%3 free
        CPWAIT(0);
        __syncthreads();
        if (c + 2 < NCHUNK) load_chunk((c + 2) % NSTAGE, c + 2);

        // ks=2 (prefetch ks=3), ks=3 (prefetch NEXT CHUNK's ks=0)
        ksstep(t0 + 2, true, aA[0] ^ 96u, aA[1] ^ 96u, aA[2] ^ 96u, aA[3] ^ 96u);
        const bool pf = (c + 1 < NCHUNK);
        ksstep(t0 + 3, pf, nA + offA[0], nA + offA[1], nA + offA[2], nA + offA[3]);
    }

    // ---- epilogue: gates + cell update in-register ----
    const int a4 = lane & 3;
    #pragma unroll
    for (int mt = 0; mt < 4; mt++) {
        #pragma unroll
        for (int rh = 0; rh < 2; rh++) {
            const int row = rowBase + wm * 64 + mt * 16 + (lane >> 2) + rh * 8;
            const float xr = is_l0 ? xvec[row] : 0.0f;
            #pragma unroll
            for (int g16 = 0; g16 < 2; g16++) {
                const int nl = wn * 32 + g16 * 16 + a4 * 2;     // n' of gate0
                const int u  = blockIdx.x * 32 + wn * 8 + g16 * 4 + a4;
                float zi = acc[mt][g16 * 2 + 0][rh * 2 + 0] + biasp[nBase + nl];
                float zf = acc[mt][g16 * 2 + 0][rh * 2 + 1] + biasp[nBase + nl + 1];
                float zg = acc[mt][g16 * 2 + 1][rh * 2 + 0] + biasp[nBase + nl + 8];
                float zo = acc[mt][g16 * 2 + 1][rh * 2 + 1] + biasp[nBase + nl + 9];
                if (is_l0) {
                    zi += xr * g_wx0p[nBase + nl];
                    zf += xr * g_wx0p[nBase + nl + 1];
                    zg += xr * g_wx0p[nBase + nl + 8];
                    zo += xr * g_wx0p[nBase + nl + 9];
                }
                const float ig = sigm(zi);
                const float fg = sigm(zf);
                const float gg = tanha(zg);
                const float og = sigm(zo);
                const size_t off = (size_t)row * Hdim + u;
                const float cn = fg * c_in[off] + ig * gg;
                c_out[off] = cn;
                const float hv = og * tanha(cn);
                if (h_out_f) h_out_f[off] = hv;
                else         h_out_h[off] = __float2half_rn(hv);
            }
        }
    }
}

// ---------------- prediction head ----------------
__global__ void head_kernel(const float* __restrict__ h,
                            const float* __restrict__ Wd,
                            const float* __restrict__ bd,
                            float* __restrict__ out)
{
    int warpg = (blockIdx.x * blockDim.x + threadIdx.x) >> 5;
    int lane = threadIdx.x & 31;
    const float4* hp = (const float4*)(h + (size_t)warpg * Hdim);
    const float4* wp = (const float4*)Wd;
    float s = 0.0f;
    #pragma unroll
    for (int i = 0; i < 8; i++) {
        float4 a = hp[lane + i * 32];
        float4 w = wp[lane + i * 32];
        s += a.x * w.x + a.y * w.y + a.z * w.z + a.w * w.w;
    }
    #pragma unroll
    for (int o = 16; o; o >>= 1) s += __shfl_xor_sync(0xffffffffu, s, o);
    if (lane == 0) out[warpg] = s + bd[0];
}

extern "C" void kernel_launch(void* const* d_in, const int* in_sizes, int n_in,
                              void* d_out, int out_size)
{
    const float* x   = (const float*)d_in[0];
    const float* c0  = (const float*)d_in[1];
    const float* h0  = (const float*)d_in[2];
    const float* Wx0 = (const float*)d_in[3];
    const float* Wh0 = (const float*)d_in[4];
    const float* b0  = (const float*)d_in[5];
    const float* Wx  = (const float*)d_in[6];
    const float* Wh  = (const float*)d_in[7];
    const float* bb  = (const float*)d_in[8];
    const float* Wd  = (const float*)d_in[9];
    const float* bd  = (const float*)d_in[10];
    float* out = (float*)d_out;  // [c | h | x_pred]

    cudaFuncSetAttribute(lstm_layer_kernel,
                         cudaFuncAttributeMaxDynamicSharedMemorySize, SMEM_TOTAL);

    wprep_kernel<<<4 * 64 * 16, 256>>>(Wh0, Wx, Wh);
    hprep_kernel<<<(Bsz * Hdim / 4) / 256, 256>>>((const float4*)h0);
    bprep_kernel<<<(5 * G4) / 256, 256>>>(b0, bb, Wx0);

    dim3 grid(G4 / BN, Bsz / BM);   // 32 x 64 = 2048 CTAs
    for (int l = 0; l < 4; l++)
        lstm_layer_kernel<<<grid, NTH, SMEM_TOTAL>>>(l, x, c0, out);

    head_kernel<<<Bsz / 8, 256>>>(out + (size_t)Bsz * Hdim, Wd, bd,
                                  out + 2ull * (size_t)Bsz * Hdim);
}

// round 13
// speedup vs baseline: 1.7464x; 1.7464x over previous
#include <cuda_runtime.h>
#include <cuda_fp16.h>
#include <cstdint>
#include <math.h>

#define Bsz 8192
#define Hdim 1024
#define G4 4096
#define HG (1024 * 4096)

#define BM 128      // batch rows per CTA
#define BN 128      // permuted z-cols per CTA (= 32 units x 4 gates)
#define BK 64       // K per pipeline chunk (4 k16-steps)
#define NCHUNK (Hdim / BK)   // 16
#define NSTAGE 3
#define NTH 256

#define STAGE_BYTES 32768    // A: 16KB swizzled + B: 16KB swizzled
#define STB_OFF 16384
#define MBAR_OFF (NSTAGE * STAGE_BYTES)
#define SMEM_TOTAL (NSTAGE * STAGE_BYTES + 2048)   // align pad + mbars

// ---------------- device scratch (allocation-free) ----------------
// g_W: B in STAGED-BLOCK layout: 16KB block per [l][bx(32)][c(16)]
//   block content: half at kr*128B + 16*(nn ^ (kr&7)) + (u&7)*2  (SW128 image)
__device__ __align__(256) __half g_W[4ull * HG];
// h buffers in STAGED-BLOCK layout: 16KB block per [by(64)][c(16)]
//   block content: half at r*128B + 16*(k16 ^ (r&7)) + (k&7)*2
__device__ __align__(256) __half g_h0s[Bsz * Hdim];
__device__ __align__(256) __half g_has[Bsz * Hdim];
__device__ __align__(256) __half g_hbs[Bsz * Hdim];
__device__ float  g_ca[Bsz * Hdim];
__device__ float  g_cb[Bsz * Hdim];
__device__ float  g_biasp[4 * G4];       // permuted biases per layer
__device__ float  g_wx0p[G4];            // permuted Wx0

// permuted column layout: n' = (u>>2)*16 + (gate>>1)*8 + (u&3)*2 + (gate&1)
__device__ __forceinline__ int np_to_col(int np) {
    int u = ((np >> 4) << 2) | ((np >> 1) & 3);
    int gate = (((np >> 3) & 1) << 1) | (np & 1);
    return gate * 1024 + u;
}
__device__ __forceinline__ uint32_t smem_u32(const void* p) {
    uint32_t a;
    asm("{ .reg .u64 t; cvta.to.shared.u64 t, %1; cvt.u32.u64 %0, t; }" : "=r"(a) : "l"(p));
    return a;
}
__device__ __forceinline__ float sigm(float z) { return 1.0f / (1.0f + __expf(-z)); }
__device__ __forceinline__ float tanha(float x) {
    float r; asm("tanh.approx.f32 %0, %1;" : "=f"(r) : "f"(x)); return r;
}

#define MBAR_INIT(a, n) \
    asm volatile("mbarrier.init.shared.b64 [%0], %1;" :: "r"(a), "r"((uint32_t)(n)) : "memory")
#define MBAR_EXPECT(a, b) \
    asm volatile("mbarrier.arrive.expect_tx.shared.b64 _, [%0], %1;" :: "r"(a), "r"((uint32_t)(b)) : "memory")
#define BULKCP(dst, src, n, mb)                                               \
    asm volatile("cp.async.bulk.shared::cluster.global.mbarrier::complete_tx::bytes " \
                 "[%0], [%1], %2, [%3];"                                      \
                 :: "r"(dst), "l"(src), "r"((uint32_t)(n)), "r"(mb) : "memory")
#define MBAR_WAIT(a, par) do {                                                    \
    asm volatile(                                                                 \
        "{\n\t.reg .pred P1;\n\t"                                                 \
        "WL%=:\n\t"                                                               \
        "mbarrier.try_wait.parity.acquire.cta.shared::cta.b64 P1, [%0], %1, 0x989680;\n\t" \
        "@P1 bra.uni WD%=;\n\t"                                                   \
        "bra.uni WL%=;\n\t"                                                       \
        "WD%=:\n\t}"                                                              \
        :: "r"(a), "r"((uint32_t)(par)) : "memory");                              \
} while (0)

#define LDSM4(r0, r1, r2, r3, a)                                              \
    asm volatile("ldmatrix.sync.aligned.m8n8.x4.shared.b16 {%0,%1,%2,%3}, [%4];" \
                 : "=r"(r0), "=r"(r1), "=r"(r2), "=r"(r3) : "r"(a))
#define LDSM4T(r0, r1, r2, r3, a)                                             \
    asm volatile("ldmatrix.sync.aligned.m8n8.x4.trans.shared.b16 {%0,%1,%2,%3}, [%4];" \
                 : "=r"(r0), "=r"(r1), "=r"(r2), "=r"(r3) : "r"(a))

__device__ __forceinline__ void mma16816(float* d, const uint32_t* a,
                                         uint32_t b0, uint32_t b1) {
    asm volatile(
        "mma.sync.aligned.m16n8k16.row.col.f32.f16.f16.f32 "
        "{%0,%1,%2,%3}, {%4,%5,%6,%7}, {%8,%9}, {%0,%1,%2,%3};\n"
        : "+f"(d[0]), "+f"(d[1]), "+f"(d[2]), "+f"(d[3])
        : "r"(a[0]), "r"(a[1]), "r"(a[2]), "r"(a[3]), "r"(b0), "r"(b1));
}

// ---------------- prep kernels ----------------
// Fold Wx+Wh, permute, fp16, emit STAGED 16KB blocks (swizzle pre-applied).
__global__ void wprep_kernel(const float4* __restrict__ Wh0,
                             const float4* __restrict__ Wx,
                             const float4* __restrict__ Wh) {
    size_t idx = (size_t)blockIdx.x * blockDim.x + threadIdx.x;  // < 4*1024*256
    int u4 = (int)(idx & 255);
    size_t kl = idx >> 8;             // l*1024 + k
    int l = (int)(kl >> 10);
    int k = (int)(kl & 1023);
    __half out[16];
    #pragma unroll
    for (int gate = 0; gate < 4; gate++) {
        size_t col4 = (size_t)(gate * 1024 + u4 * 4) >> 2;
        float4 v;
        if (l == 0) {
            v = Wh0[(size_t)k * 1024 + col4];
        } else {
            size_t o = (size_t)(l - 1) * (HG / 4) + (size_t)k * 1024 + col4;
            float4 a = Wx[o], b = Wh[o];
            v.x = a.x + b.x; v.y = a.y + b.y; v.z = a.z + b.z; v.w = a.w + b.w;
        }
        int base = ((gate >> 1) << 3) | (gate & 1);
        out[base + 0] = __float2half_rn(v.x);
        out[base + 2] = __float2half_rn(v.y);
        out[base + 4] = __float2half_rn(v.z);
        out[base + 6] = __float2half_rn(v.w);
    }
    // two 16B units: n16 = u4*2 + j  (same bx for both)
    int c = k >> 6, kr = k & 63;
    #pragma unroll
    for (int j = 0; j < 2; j++) {
        int n16 = u4 * 2 + j;
        int bx = n16 >> 4, nn = n16 & 15;
        size_t half_off = (((size_t)l * 32 + bx) * 16 + c) * 8192
                          + kr * 128 + 8 * (nn ^ (kr & 7));
        *(uint4*)(g_W + half_off) = ((const uint4*)out)[j];
    }
}
// h0 -> staged blocks
__global__ void hprep_kernel(const float4* __restrict__ h0) {
    size_t idx = (size_t)blockIdx.x * blockDim.x + threadIdx.x;  // < Bsz*128
    int row = (int)(idx >> 7);
    int k16 = (int)(idx & 127);
    float4 v0 = h0[(size_t)row * 256 + k16 * 2];
    float4 v1 = h0[(size_t)row * 256 + k16 * 2 + 1];
    __half out[8];
    out[0] = __float2half_rn(v0.x); out[1] = __float2half_rn(v0.y);
    out[2] = __float2half_rn(v0.z); out[3] = __float2half_rn(v0.w);
    out[4] = __float2half_rn(v1.x); out[5] = __float2half_rn(v1.y);
    out[6] = __float2half_rn(v1.z); out[7] = __float2half_rn(v1.w);
    int blk = (row >> 7) * 16 + (k16 >> 3);
    int r = row & 127, kk = k16 & 7;
    size_t half_off = (size_t)blk * 8192 + r * 64 + 8 * (kk ^ (r & 7));
    *(uint4*)(g_h0s + half_off) = *(const uint4*)out;
}
__global__ void bprep_kernel(const float* __restrict__ b0,
                             const float* __restrict__ bb,
                             const float* __restrict__ Wx0) {
    int idx = blockIdx.x * blockDim.x + threadIdx.x;   // < 5*4096
    int np = idx & 4095;
    int l = idx >> 12;
    int col = np_to_col(np);
    if (l < 4) {
        g_biasp[idx] = (l == 0) ? b0[col] : bb[(l - 1) * G4 + col];
    } else {
        g_wx0p[np] = Wx0[col];
    }
}

// ------- fused LSTM layer: R7 pipeline, staging via cp.async.bulk ----------
__global__ void __launch_bounds__(NTH, 2)
lstm_layer_kernel(int layer,
                  const float* __restrict__ xvec,
                  const float* __restrict__ c0ext,
                  float* __restrict__ dout)
{
    const __half *A;
    const float *c_in;
    float *c_out;
    __half *h_out_h;      // staged layout (layers 0-2)
    float *h_out_f;       // fp32 row-major (layer 3)
    if (layer == 0) {
        A = g_h0s; c_in = c0ext;
        c_out = g_ca; h_out_h = g_has; h_out_f = nullptr;
    } else if (layer == 1) {
        A = g_has; c_in = g_ca;
        c_out = g_cb; h_out_h = g_hbs; h_out_f = nullptr;
    } else if (layer == 2) {
        A = g_hbs; c_in = g_cb;
        c_out = g_ca; h_out_h = g_has; h_out_f = nullptr;
    } else {
        A = g_has; c_in = g_ca;
        c_out = dout; h_out_h = nullptr; h_out_f = dout + (size_t)Bsz * Hdim;
    }
    const bool is_l0 = (layer == 0);
    const float* biasp = g_biasp + layer * G4;

    extern __shared__ char smem_raw[];
    const uint32_t sb = (smem_u32(smem_raw) + 1023u) & ~1023u;  // 1024-align
    const int tid  = threadIdx.x;
    const int lane = tid & 31;
    const int wid  = tid >> 5;
    const int wm   = wid >> 2;        // 0..1  (64 m rows each)
    const int wn   = wid & 3;         // 0..3  (32 n' cols each)
    const int rowBase = blockIdx.y * BM;
    const int nBase   = blockIdx.x * BN;

    const char* AsrcBase = (const char*)A + (size_t)blockIdx.y * 16 * 16384;
    const char* BsrcBase = (const char*)g_W
        + (((size_t)layer * 32 + blockIdx.x) * 16) * 16384;

    // mbarriers
    if (tid == 0) {
        #pragma unroll
        for (int s = 0; s < NSTAGE; s++) MBAR_INIT(sb + MBAR_OFF + s * 8, 1);
    }
    __syncthreads();

    auto issue_chunk = [&](int c) {
        if (tid == 0) {
            const int s = c % NSTAGE;
            const uint32_t mb = sb + MBAR_OFF + s * 8;
            const uint32_t st = sb + s * STAGE_BYTES;
            MBAR_EXPECT(mb, STAGE_BYTES);
            BULKCP(st, AsrcBase + (size_t)c * 16384, 16384, mb);
            BULKCP(st + STB_OFF, BsrcBase + (size_t)c * 16384, 16384, mb);
        }
    };

    float acc[4][4][4];
    #pragma unroll
    for (int mt = 0; mt < 4; mt++)
        #pragma unroll
        for (int j = 0; j < 4; j++)
            #pragma unroll
            for (int r = 0; r < 4; r++) acc[mt][j][r] = 0.0f;

    // per-lane ldmatrix base-address components (ks=0)
    const int arow = wm * 64 + (lane & 15);              // per mt: +mt*16
    const int ahi  = lane >> 4;                          // 0/1 (k-half unit)
    const int bm   = lane >> 3;                          // matrix id 0..3
    const int br   = lane & 7;                           // row within 8
    const int bkoff = br + (bm & 1) * 8;                 // k row offset within 16
    const int bnunit = wn * 4 + (bm >> 1);               // n' 16B-unit

    uint32_t offA[4], offB[2];
    #pragma unroll
    for (int mt = 0; mt < 4; mt++) {
        int rr = arow + mt * 16;
        offA[mt] = (uint32_t)(rr * 128 + 16 * (ahi ^ (rr & 7)));
    }
    #pragma unroll
    for (int jp = 0; jp < 2; jp++)
        offB[jp] = (uint32_t)(bkoff * 256 + 16 * ((bnunit + jp * 2) ^ (bkoff & 7)));

    uint32_t af[4][4];        // A frags, rolling per-mt reload
    uint32_t bf[2][4][2];     // B frags, double-buffered over ks

    auto ksstep = [&](int cur, bool pf,
                      uint32_t pa0, uint32_t pa1, uint32_t pa2, uint32_t pa3,
                      uint32_t pb0, uint32_t pb1) {
        #pragma unroll
        for (int j = 0; j < 4; j++)
            mma16816(acc[0][j], af[0], bf[cur][j][0], bf[cur][j][1]);
        if (pf) {
            uint32_t r0, r1, r2, r3;
            LDSM4T(r0, r1, r2, r3, pb0);
            bf[cur ^ 1][0][0] = r0; bf[cur ^ 1][0][1] = r1;
            bf[cur ^ 1][1][0] = r2; bf[cur ^ 1][1][1] = r3;
            LDSM4T(r0, r1, r2, r3, pb1);
            bf[cur ^ 1][2][0] = r0; bf[cur ^ 1][2][1] = r1;
            bf[cur ^ 1][3][0] = r2; bf[cur ^ 1][3][1] = r3;
            LDSM4(af[0][0], af[0][1], af[0][2], af[0][3], pa0);
        }
        #pragma unroll
        for (int j = 0; j < 4; j++)
            mma16816(acc[1][j], af[1], bf[cur][j][0], bf[cur][j][1]);
        if (pf) LDSM4(af[1][0], af[1][1], af[1][2], af[1][3], pa1);
        #pragma unroll
        for (int j = 0; j < 4; j++)
            mma16816(acc[2][j], af[2], bf[cur][j][0], bf[cur][j][1]);
        if (pf) LDSM4(af[2][0], af[2][1], af[2][2], af[2][3], pa2);
        #pragma unroll
        for (int j = 0; j < 4; j++)
            mma16816(acc[3][j], af[3], bf[cur][j][0], bf[cur][j][1]);
        if (pf) LDSM4(af[3][0], af[3][1], af[3][2], af[3][3], pa3);
    };

    // prologue: issue stages 0,1; wait stage 0; load ks0 fragments
    issue_chunk(0);
    issue_chunk(1);
    MBAR_WAIT(sb + MBAR_OFF, 0);
    {
        const uint32_t stA = sb;
        const uint32_t stB = stA + STB_OFF;
        #pragma unroll
        for (int mt = 0; mt < 4; mt++)
            LDSM4(af[mt][0], af[mt][1], af[mt][2], af[mt][3], stA + offA[mt]);
        uint32_t r0, r1, r2, r3;
        LDSM4T(r0, r1, r2, r3, stB + offB[0]);
        bf[0][0][0] = r0; bf[0][0][1] = r1; bf[0][1][0] = r2; bf[0][1][1] = r3;
        LDSM4T(r0, r1, r2, r3, stB + offB[1]);
        bf[0][2][0] = r0; bf[0][2][1] = r1; bf[0][3][0] = r2; bf[0][3][1] = r3;
    }

    for (int c = 0; c < NCHUNK; c++) {
        const int s = c % NSTAGE;
        const uint32_t stA = sb + s * STAGE_BYTES;
        const uint32_t stB = stA + STB_OFF;
        uint32_t aA[4];
        #pragma unroll
        for (int mt = 0; mt < 4; mt++) aA[mt] = stA + offA[mt];
        const uint32_t b0A = stB + offB[0];
        const uint32_t b1A = stB + offB[1];
        const uint32_t nA = sb + ((c + 1) % NSTAGE) * STAGE_BYTES;
        const uint32_t nB = nA + STB_OFF;

        // ks=0, ks=1 (prefetch next ks within this stage)
        ksstep(0, true, aA[0] ^ 32u, aA[1] ^ 32u, aA[2] ^ 32u, aA[3] ^ 32u,
               b0A + 4096, b1A + 4096);
        ksstep(1, true, aA[0] ^ 64u, aA[1] ^ 64u, aA[2] ^ 64u, aA[3] ^ 64u,
               b0A + 8192, b1A + 8192);

        // mid-chunk: wait next chunk's data; WAR barrier; re-arm stage c+2
        if (c + 1 < NCHUNK)
            MBAR_WAIT(sb + MBAR_OFF + ((c + 1) % NSTAGE) * 8, ((c + 1) / NSTAGE) & 1);
        __syncthreads();
        if (c + 2 < NCHUNK) issue_chunk(c + 2);

        // ks=2 (prefetch ks=3), ks=3 (prefetch NEXT CHUNK's ks=0)
        ksstep(0, true, aA[0] ^ 96u, aA[1] ^ 96u, aA[2] ^ 96u, aA[3] ^ 96u,
               b0A + 12288, b1A + 12288);
        const bool pf = (c + 1 < NCHUNK);
        ksstep(1, pf, nA + offA[0], nA + offA[1], nA + offA[2], nA + offA[3],
               nB + offB[0], nB + offB[1]);
    }

    // ---- epilogue: gates + cell update; h written in staged layout ----
    const int a4 = lane & 3;
    #pragma unroll
    for (int mt = 0; mt < 4; mt++) {
        #pragma unroll
        for (int rh = 0; rh < 2; rh++) {
            const int row = rowBase + wm * 64 + mt * 16 + (lane >> 2) + rh * 8;
            const float xr = is_l0 ? xvec[row] : 0.0f;
            #pragma unroll
            for (int g16 = 0; g16 < 2; g16++) {
                const int nl = wn * 32 + g16 * 16 + a4 * 2;     // n' of gate0
                const int u  = blockIdx.x * 32 + wn * 8 + g16 * 4 + a4;
                float zi = acc[mt][g16 * 2 + 0][rh * 2 + 0] + biasp[nBase + nl];
                float zf = acc[mt][g16 * 2 + 0][rh * 2 + 1] + biasp[nBase + nl + 1];
                float zg = acc[mt][g16 * 2 + 1][rh * 2 + 0] + biasp[nBase + nl + 8];
                float zo = acc[mt][g16 * 2 + 1][rh * 2 + 1] + biasp[nBase + nl + 9];
                if (is_l0) {
                    zi += xr * g_wx0p[nBase + nl];
                    zf += xr * g_wx0p[nBase + nl + 1];
                    zg += xr * g_wx0p[nBase + nl + 8];
                    zo += xr * g_wx0p[nBase + nl + 9];
                }
                const float ig = sigm(zi);
                const float fg = sigm(zf);
                const float gg = tanha(zg);
                const float og = sigm(zo);
                const size_t off = (size_t)row * Hdim + u;
                const float cn = fg * c_in[off] + ig * gg;
                c_out[off] = cn;
                const float hv = og * tanha(cn);
                if (h_out_f) {
                    h_out_f[off] = hv;
                } else {
                    int blk = (row >> 7) * 16 + (u >> 6);
                    int r = row & 127, k16 = (u >> 3) & 7, kk = u & 7;
                    size_t hoff = (size_t)blk * 8192 + r * 64
                                  + 8 * (k16 ^ (r & 7)) + kk;
                    h_out_h[hoff] = __float2half_rn(hv);
                }
            }
        }
    }
}

// ---------------- prediction head ----------------
__global__ void head_kernel(const float* __restrict__ h,
                            const float* __restrict__ Wd,
                            const float* __restrict__ bd,
                            float* __restrict__ out)
{
    int warpg = (blockIdx.x * blockDim.x + threadIdx.x) >> 5;
    int lane = threadIdx.x & 31;
    const float4* hp = (const float4*)(h + (size_t)warpg * Hdim);
    const float4* wp = (const float4*)Wd;
    float s = 0.0f;
    #pragma unroll
    for (int i = 0; i < 8; i++) {
        float4 a = hp[lane + i * 32];
        float4 w = wp[lane + i * 32];
        s += a.x * w.x + a.y * w.y + a.z * w.z + a.w * w.w;
    }
    #pragma unroll
    for (int o = 16; o; o >>= 1) s += __shfl_xor_sync(0xffffffffu, s, o);
    if (lane == 0) out[warpg] = s + bd[0];
}

extern "C" void kernel_launch(void* const* d_in, const int* in_sizes, int n_in,
                              void* d_out, int out_size)
{
    const float* x   = (const float*)d_in[0];
    const float* c0  = (const float*)d_in[1];
    const float* h0  = (const float*)d_in[2];
    const float* Wx0 = (const float*)d_in[3];
    const float* Wh0 = (const float*)d_in[4];
    const float* b0  = (const float*)d_in[5];
    const float* Wx  = (const float*)d_in[6];
    const float* Wh  = (const float*)d_in[7];
    const float* bb  = (const float*)d_in[8];
    const float* Wd  = (const float*)d_in[9];
    const float* bd  = (const float*)d_in[10];
    float* out = (float*)d_out;  // [c | h | x_pred]

    cudaFuncSetAttribute(lstm_layer_kernel,
                         cudaFuncAttributeMaxDynamicSharedMemorySize, SMEM_TOTAL);

    wprep_kernel<<<(4 * 1024 * 256) / 256, 256>>>((const float4*)Wh0,
                                                  (const float4*)Wx,
                                                  (const float4*)Wh);
    hprep_kernel<<<(Bsz * 128) / 256, 256>>>((const float4*)h0);
    bprep_kernel<<<(5 * G4) / 256, 256>>>(b0, bb, Wx0);

    dim3 grid(G4 / BN, Bsz / BM);   // 32 x 64 = 2048 CTAs
    for (int l = 0; l < 4; l++)
        lstm_layer_kernel<<<grid, NTH, SMEM_TOTAL>>>(l, x, c0, out);

    head_kernel<<<Bsz / 8, 256>>>(out + (size_t)Bsz * Hdim, Wd, bd,
                                  out + 2ull * (size_t)Bsz * Hdim);
}

// round 14
// speedup vs baseline: 1.8144x; 1.0389x over previous
#include <cuda_runtime.h>
#include <cuda_fp16.h>
#include <cstdint>
#include <math.h>

#define Bsz 8192
#define Hdim 1024
#define G4 4096
#define HG (1024 * 4096)

#define BM 128      // batch rows per CTA
#define BN 128      // permuted z-cols per CTA (= 32 units x 4 gates)
#define BK 64       // K per pipeline chunk (4 k16-steps)
#define NCHUNK (Hdim / BK)   // 16
#define NSTAGE 3
#define NTH 256

#define STAGE_BYTES 32768    // A: 16KB swizzled + B: 16KB swizzled
#define STB_OFF 16384
#define MBAR_OFF (NSTAGE * STAGE_BYTES)
#define SMEM_TOTAL (NSTAGE * STAGE_BYTES + 2048)   // align pad + mbars

// ---------------- device scratch (allocation-free) ----------------
// g_W: B in STAGED-BLOCK layout: 16KB block per [l][bx(32)][c(16)]
__device__ __align__(256) __half g_W[4ull * HG];
// h buffers in STAGED-BLOCK layout: 16KB block per [by(64)][c(16)]
__device__ __align__(256) __half g_h0s[Bsz * Hdim];
__device__ __align__(256) __half g_has[Bsz * Hdim];
__device__ __align__(256) __half g_hbs[Bsz * Hdim];
__device__ float  g_ca[Bsz * Hdim];
__device__ float  g_cb[Bsz * Hdim];
__device__ float  g_biasp[4 * G4];       // permuted biases per layer
__device__ float  g_wx0p[G4];            // permuted Wx0

// permuted column layout: n' = (u>>2)*16 + (gate>>1)*8 + (u&3)*2 + (gate&1)
__device__ __forceinline__ int np_to_col(int np) {
    int u = ((np >> 4) << 2) | ((np >> 1) & 3);
    int gate = (((np >> 3) & 1) << 1) | (np & 1);
    return gate * 1024 + u;
}
__device__ __forceinline__ uint32_t smem_u32(const void* p) {
    uint32_t a;
    asm("{ .reg .u64 t; cvta.to.shared.u64 t, %1; cvt.u32.u64 %0, t; }" : "=r"(a) : "l"(p));
    return a;
}
__device__ __forceinline__ float sigm(float z) { return 1.0f / (1.0f + __expf(-z)); }
__device__ __forceinline__ float tanha(float x) {
    float r; asm("tanh.approx.f32 %0, %1;" : "=f"(r) : "f"(x)); return r;
}

#define MBAR_INIT(a, n) \
    asm volatile("mbarrier.init.shared.b64 [%0], %1;" :: "r"(a), "r"((uint32_t)(n)) : "memory")
#define MBAR_EXPECT(a, b) \
    asm volatile("mbarrier.arrive.expect_tx.shared.b64 _, [%0], %1;" :: "r"(a), "r"((uint32_t)(b)) : "memory")
#define MBAR_ARRIVE(a) \
    asm volatile("mbarrier.arrive.shared.b64 _, [%0];" :: "r"(a) : "memory")
#define BULKCP(dst, src, n, mb)                                               \
    asm volatile("cp.async.bulk.shared::cluster.global.mbarrier::complete_tx::bytes " \
                 "[%0], [%1], %2, [%3];"                                      \
                 :: "r"(dst), "l"(src), "r"((uint32_t)(n)), "r"(mb) : "memory")
#define MBAR_WAIT(a, par) do {                                                    \
    asm volatile(                                                                 \
        "{\n\t.reg .pred P1;\n\t"                                                 \
        "WL%=:\n\t"                                                               \
        "mbarrier.try_wait.parity.acquire.cta.shared::cta.b64 P1, [%0], %1, 0x989680;\n\t" \
        "@P1 bra.uni WD%=;\n\t"                                                   \
        "bra.uni WL%=;\n\t"                                                       \
        "WD%=:\n\t}"                                                              \
        :: "r"(a), "r"((uint32_t)(par)) : "memory");                              \
} while (0)

#define LDSM4(r0, r1, r2, r3, a)                                              \
    asm volatile("ldmatrix.sync.aligned.m8n8.x4.shared.b16 {%0,%1,%2,%3}, [%4];" \
                 : "=r"(r0), "=r"(r1), "=r"(r2), "=r"(r3) : "r"(a))
#define LDSM4T(r0, r1, r2, r3, a)                                             \
    asm volatile("ldmatrix.sync.aligned.m8n8.x4.trans.shared.b16 {%0,%1,%2,%3}, [%4];" \
                 : "=r"(r0), "=r"(r1), "=r"(r2), "=r"(r3) : "r"(a))

__device__ __forceinline__ void mma16816(float* d, const uint32_t* a,
                                         uint32_t b0, uint32_t b1) {
    asm volatile(
        "mma.sync.aligned.m16n8k16.row.col.f32.f16.f16.f32 "
        "{%0,%1,%2,%3}, {%4,%5,%6,%7}, {%8,%9}, {%0,%1,%2,%3};\n"
        : "+f"(d[0]), "+f"(d[1]), "+f"(d[2]), "+f"(d[3])
        : "r"(a[0]), "r"(a[1]), "r"(a[2]), "r"(a[3]), "r"(b0), "r"(b1));
}

// ---------------- prep kernels (identical to R13) ----------------
__global__ void wprep_kernel(const float4* __restrict__ Wh0,
                             const float4* __restrict__ Wx,
                             const float4* __restrict__ Wh) {
    size_t idx = (size_t)blockIdx.x * blockDim.x + threadIdx.x;  // < 4*1024*256
    int u4 = (int)(idx & 255);
    size_t kl = idx >> 8;             // l*1024 + k
    int l = (int)(kl >> 10);
    int k = (int)(kl & 1023);
    __half out[16];
    #pragma unroll
    for (int gate = 0; gate < 4; gate++) {
        size_t col4 = (size_t)(gate * 1024 + u4 * 4) >> 2;
        float4 v;
        if (l == 0) {
            v = Wh0[(size_t)k * 1024 + col4];
        } else {
            size_t o = (size_t)(l - 1) * (HG / 4) + (size_t)k * 1024 + col4;
            float4 a = Wx[o], b = Wh[o];
            v.x = a.x + b.x; v.y = a.y + b.y; v.z = a.z + b.z; v.w = a.w + b.w;
        }
        int base = ((gate >> 1) << 3) | (gate & 1);
        out[base + 0] = __float2half_rn(v.x);
        out[base + 2] = __float2half_rn(v.y);
        out[base + 4] = __float2half_rn(v.z);
        out[base + 6] = __float2half_rn(v.w);
    }
    int c = k >> 6, kr = k & 63;
    #pragma unroll
    for (int j = 0; j < 2; j++) {
        int n16 = u4 * 2 + j;
        int bx = n16 >> 4, nn = n16 & 15;
        size_t half_off = (((size_t)l * 32 + bx) * 16 + c) * 8192
                          + kr * 128 + 8 * (nn ^ (kr & 7));
        *(uint4*)(g_W + half_off) = ((const uint4*)out)[j];
    }
}
__global__ void hprep_kernel(const float4* __restrict__ h0) {
    size_t idx = (size_t)blockIdx.x * blockDim.x + threadIdx.x;  // < Bsz*128
    int row = (int)(idx >> 7);
    int k16 = (int)(idx & 127);
    float4 v0 = h0[(size_t)row * 256 + k16 * 2];
    float4 v1 = h0[(size_t)row * 256 + k16 * 2 + 1];
    __half out[8];
    out[0] = __float2half_rn(v0.x); out[1] = __float2half_rn(v0.y);
    out[2] = __float2half_rn(v0.z); out[3] = __float2half_rn(v0.w);
    out[4] = __float2half_rn(v1.x); out[5] = __float2half_rn(v1.y);
    out[6] = __float2half_rn(v1.z); out[7] = __float2half_rn(v1.w);
    int blk = (row >> 7) * 16 + (k16 >> 3);
    int r = row & 127, kk = k16 & 7;
    size_t half_off = (size_t)blk * 8192 + r * 64 + 8 * (kk ^ (r & 7));
    *(uint4*)(g_h0s + half_off) = *(const uint4*)out;
}
__global__ void bprep_kernel(const float* __restrict__ b0,
                             const float* __restrict__ bb,
                             const float* __restrict__ Wx0) {
    int idx = blockIdx.x * blockDim.x + threadIdx.x;   // < 5*4096
    int np = idx & 4095;
    int l = idx >> 12;
    int col = np_to_col(np);
    if (l < 4) {
        g_biasp[idx] = (l == 0) ? b0[col] : bb[(l - 1) * G4 + col];
    } else {
        g_wx0p[np] = Wx0[col];
    }
}

// -- fused LSTM layer: bulk-copy staging + FREE-RUNNING warps (full/empty) --
__global__ void __launch_bounds__(NTH, 2)
lstm_layer_kernel(int layer,
                  const float* __restrict__ xvec,
                  const float* __restrict__ c0ext,
                  float* __restrict__ dout)
{
    const __half *A;
    const float *c_in;
    float *c_out;
    __half *h_out_h;      // staged layout (layers 0-2)
    float *h_out_f;       // fp32 row-major (layer 3)
    if (layer == 0) {
        A = g_h0s; c_in = c0ext;
        c_out = g_ca; h_out_h = g_has; h_out_f = nullptr;
    } else if (layer == 1) {
        A = g_has; c_in = g_ca;
        c_out = g_cb; h_out_h = g_hbs; h_out_f = nullptr;
    } else if (layer == 2) {
        A = g_hbs; c_in = g_cb;
        c_out = g_ca; h_out_h = g_has; h_out_f = nullptr;
    } else {
        A = g_has; c_in = g_ca;
        c_out = dout; h_out_h = nullptr; h_out_f = dout + (size_t)Bsz * Hdim;
    }
    const bool is_l0 = (layer == 0);
    const float* biasp = g_biasp + layer * G4;

    extern __shared__ char smem_raw[];
    const uint32_t sb = (smem_u32(smem_raw) + 1023u) & ~1023u;  // 1024-align
    const int tid  = threadIdx.x;
    const int lane = tid & 31;
    const int wid  = tid >> 5;
    const int wm   = wid >> 2;        // 0..1  (64 m rows each)
    const int wn   = wid & 3;         // 0..3  (32 n' cols each)
    const int rowBase = blockIdx.y * BM;
    const int nBase   = blockIdx.x * BN;

    const char* AsrcBase = (const char*)A + (size_t)blockIdx.y * 16 * 16384;
    const char* BsrcBase = (const char*)g_W
        + (((size_t)layer * 32 + blockIdx.x) * 16) * 16384;

    // mbarriers: full[s] at MBAR_OFF + s*8 (count 1, tx); empty[s] at +24+s*8 (count 8)
    if (tid == 0) {
        #pragma unroll
        for (int s = 0; s < NSTAGE; s++) {
            MBAR_INIT(sb + MBAR_OFF + s * 8, 1);
            MBAR_INIT(sb + MBAR_OFF + 24 + s * 8, 8);
        }
    }
    __syncthreads();

    auto issue_chunk = [&](int c) {
        const int s = c % NSTAGE;
        const uint32_t mb = sb + MBAR_OFF + s * 8;
        const uint32_t st = sb + s * STAGE_BYTES;
        MBAR_EXPECT(mb, STAGE_BYTES);
        BULKCP(st, AsrcBase + (size_t)c * 16384, 16384, mb);
        BULKCP(st + STB_OFF, BsrcBase + (size_t)c * 16384, 16384, mb);
    };

    float acc[4][4][4];
    #pragma unroll
    for (int mt = 0; mt < 4; mt++)
        #pragma unroll
        for (int j = 0; j < 4; j++)
            #pragma unroll
            for (int r = 0; r < 4; r++) acc[mt][j][r] = 0.0f;

    // per-lane ldmatrix base-address components (ks=0)
    const int arow = wm * 64 + (lane & 15);              // per mt: +mt*16
    const int ahi  = lane >> 4;                          // 0/1 (k-half unit)
    const int bm   = lane >> 3;                          // matrix id 0..3
    const int br   = lane & 7;                           // row within 8
    const int bkoff = br + (bm & 1) * 8;                 // k row offset within 16
    const int bnunit = wn * 4 + (bm >> 1);               // n' 16B-unit

    uint32_t offA[4], offB[2];
    #pragma unroll
    for (int mt = 0; mt < 4; mt++) {
        int rr = arow + mt * 16;
        offA[mt] = (uint32_t)(rr * 128 + 16 * (ahi ^ (rr & 7)));
    }
    #pragma unroll
    for (int jp = 0; jp < 2; jp++)
        offB[jp] = (uint32_t)(bkoff * 256 + 16 * ((bnunit + jp * 2) ^ (bkoff & 7)));

    uint32_t af[4][4];        // A frags, rolling per-mt reload
    uint32_t bf[2][4][2];     // B frags, double-buffered over ks

    auto ksstep = [&](int cur, bool pf,
                      uint32_t pa0, uint32_t pa1, uint32_t pa2, uint32_t pa3,
                      uint32_t pb0, uint32_t pb1) {
        #pragma unroll
        for (int j = 0; j < 4; j++)
            mma16816(acc[0][j], af[0], bf[cur][j][0], bf[cur][j][1]);
        if (pf) {
            uint32_t r0, r1, r2, r3;
            LDSM4T(r0, r1, r2, r3, pb0);
            bf[cur ^ 1][0][0] = r0; bf[cur ^ 1][0][1] = r1;
            bf[cur ^ 1][1][0] = r2; bf[cur ^ 1][1][1] = r3;
            LDSM4T(r0, r1, r2, r3, pb1);
            bf[cur ^ 1][2][0] = r0; bf[cur ^ 1][2][1] = r1;
            bf[cur ^ 1][3][0] = r2; bf[cur ^ 1][3][1] = r3;
            LDSM4(af[0][0], af[0][1], af[0][2], af[0][3], pa0);
        }
        #pragma unroll
        for (int j = 0; j < 4; j++)
            mma16816(acc[1][j], af[1], bf[cur][j][0], bf[cur][j][1]);
        if (pf) LDSM4(af[1][0], af[1][1], af[1][2], af[1][3], pa1);
        #pragma unroll
        for (int j = 0; j < 4; j++)
            mma16816(acc[2][j], af[2], bf[cur][j][0], bf[cur][j][1]);
        if (pf) LDSM4(af[2][0], af[2][1], af[2][2], af[2][3], pa2);
        #pragma unroll
        for (int j = 0; j < 4; j++)
            mma16816(acc[3][j], af[3], bf[cur][j][0], bf[cur][j][1]);
        if (pf) LDSM4(af[3][0], af[3][1], af[3][2], af[3][3], pa3);
    };

    // prologue: issue all 3 stages; wait stage 0; load ks0 fragments
    if (tid == 0) {
        issue_chunk(0);
        issue_chunk(1);
        issue_chunk(2);
    }
    MBAR_WAIT(sb + MBAR_OFF, 0);
    {
        const uint32_t stA = sb;
        const uint32_t stB = stA + STB_OFF;
        #pragma unroll
        for (int mt = 0; mt < 4; mt++)
            LDSM4(af[mt][0], af[mt][1], af[mt][2], af[mt][3], stA + offA[mt]);
        uint32_t r0, r1, r2, r3;
        LDSM4T(r0, r1, r2, r3, stB + offB[0]);
        bf[0][0][0] = r0; bf[0][0][1] = r1; bf[0][1][0] = r2; bf[0][1][1] = r3;
        LDSM4T(r0, r1, r2, r3, stB + offB[1]);
        bf[0][2][0] = r0; bf[0][2][1] = r1; bf[0][3][0] = r2; bf[0][3][1] = r3;
    }

    for (int c = 0; c < NCHUNK; c++) {
        const int s = c % NSTAGE;
        const uint32_t stA = sb + s * STAGE_BYTES;
        const uint32_t stB = stA + STB_OFF;
        uint32_t aA[4];
        #pragma unroll
        for (int mt = 0; mt < 4; mt++) aA[mt] = stA + offA[mt];
        const uint32_t b0A = stB + offB[0];
        const uint32_t b1A = stB + offB[1];
        const uint32_t nA = sb + ((c + 1) % NSTAGE) * STAGE_BYTES;
        const uint32_t nB = nA + STB_OFF;

        // ks=0..2: mma + intra-stage fragment prefetch (last stage-s read at ks2)
        ksstep(0, true, aA[0] ^ 32u, aA[1] ^ 32u, aA[2] ^ 32u, aA[3] ^ 32u,
               b0A + 4096, b1A + 4096);
        ksstep(1, true, aA[0] ^ 64u, aA[1] ^ 64u, aA[2] ^ 64u, aA[3] ^ 64u,
               b0A + 8192, b1A + 8192);
        ksstep(0, true, aA[0] ^ 96u, aA[1] ^ 96u, aA[2] ^ 96u, aA[3] ^ 96u,
               b0A + 12288, b1A + 12288);

        // wait next chunk's data (per-warp, no CTA barrier)
        if (c + 1 < NCHUNK)
            MBAR_WAIT(sb + MBAR_OFF + ((c + 1) % NSTAGE) * 8, ((c + 1) / NSTAGE) & 1);

        // ks=3: consumes ks2-loaded frags (forces LDSM completion), prefetches
        // next chunk's ks0 from stage (c+1)%3
        const bool pf = (c + 1 < NCHUNK);
        ksstep(1, pf, nA + offA[0], nA + offA[1], nA + offA[2], nA + offA[3],
               nB + offB[0], nB + offB[1]);

        // this warp is done with stage s
        if (lane == 0) MBAR_ARRIVE(sb + MBAR_OFF + 24 + s * 8);
        // producer: re-issue stage s for chunk c+3 once all warps drained chunk c
        if (tid == 0 && c + 3 < NCHUNK) {
            MBAR_WAIT(sb + MBAR_OFF + 24 + s * 8, (c / NSTAGE) & 1);
            issue_chunk(c + 3);
        }
    }

    // ---- epilogue: gates + cell update; h written in staged layout ----
    const int a4 = lane & 3;
    #pragma unroll
    for (int mt = 0; mt < 4; mt++) {
        #pragma unroll
        for (int rh = 0; rh < 2; rh++) {
            const int row = rowBase + wm * 64 + mt * 16 + (lane >> 2) + rh * 8;
            const float xr = is_l0 ? xvec[row] : 0.0f;
            #pragma unroll
            for (int g16 = 0; g16 < 2; g16++) {
                const int nl = wn * 32 + g16 * 16 + a4 * 2;     // n' of gate0
                const int u  = blockIdx.x * 32 + wn * 8 + g16 * 4 + a4;
                float zi = acc[mt][g16 * 2 + 0][rh * 2 + 0] + biasp[nBase + nl];
                float zf = acc[mt][g16 * 2 + 0][rh * 2 + 1] + biasp[nBase + nl + 1];
                float zg = acc[mt][g16 * 2 + 1][rh * 2 + 0] + biasp[nBase + nl + 8];
                float zo = acc[mt][g16 * 2 + 1][rh * 2 + 1] + biasp[nBase + nl + 9];
                if (is_l0) {
                    zi += xr * g_wx0p[nBase + nl];
                    zf += xr * g_wx0p[nBase + nl + 1];
                    zg += xr * g_wx0p[nBase + nl + 8];
                    zo += xr * g_wx0p[nBase + nl + 9];
                }
                const float ig = sigm(zi);
                const float fg = sigm(zf);
                const float gg = tanha(zg);
                const float og = sigm(zo);
                const size_t off = (size_t)row * Hdim + u;
                const float cn = fg * c_in[off] + ig * gg;
                c_out[off] = cn;
                const float hv = og * tanha(cn);
                if (h_out_f) {
                    h_out_f[off] = hv;
                } else {
                    int blk = (row >> 7) * 16 + (u >> 6);
                    int r = row & 127, k16 = (u >> 3) & 7, kk = u & 7;
                    size_t hoff = (size_t)blk * 8192 + r * 64
                                  + 8 * (k16 ^ (r & 7)) + kk;
                    h_out_h[hoff] = __float2half_rn(hv);
                }
            }
        }
    }
}

// ---------------- prediction head ----------------
__global__ void head_kernel(const float* __restrict__ h,
                            const float* __restrict__ Wd,
                            const float* __restrict__ bd,
                            float* __restrict__ out)
{
    int warpg = (blockIdx.x * blockDim.x + threadIdx.x) >> 5;
    int lane = threadIdx.x & 31;
    const float4* hp = (const float4*)(h + (size_t)warpg * Hdim);
    const float4* wp = (const float4*)Wd;
    float s = 0.0f;
    #pragma unroll
    for (int i = 0; i < 8; i++) {
        float4 a = hp[lane + i * 32];
        float4 w = wp[lane + i * 32];
        s += a.x * w.x + a.y * w.y + a.z * w.z + a.w * w.w;
    }
    #pragma unroll
    for (int o = 16; o; o >>= 1) s += __shfl_xor_sync(0xffffffffu, s, o);
    if (lane == 0) out[warpg] = s + bd[0];
}

extern "C" void kernel_launch(void* const* d_in, const int* in_sizes, int n_in,
                              void* d_out, int out_size)
{
    const float* x   = (const float*)d_in[0];
    const float* c0  = (const float*)d_in[1];
    const float* h0  = (const float*)d_in[2];
    const float* Wx0 = (const float*)d_in[3];
    const float* Wh0 = (const float*)d_in[4];
    const float* b0  = (const float*)d_in[5];
    const float* Wx  = (const float*)d_in[6];
    const float* Wh  = (const float*)d_in[7];
    const float* bb  = (const float*)d_in[8];
    const float* Wd  = (const float*)d_in[9];
    const float* bd  = (const float*)d_in[10];
    float* out = (float*)d_out;  // [c | h | x_pred]

    cudaFuncSetAttribute(lstm_layer_kernel,
                         cudaFuncAttributeMaxDynamicSharedMemorySize, SMEM_TOTAL);

    wprep_kernel<<<(4 * 1024 * 256) / 256, 256>>>((const float4*)Wh0,
                                                  (const float4*)Wx,
                                                  (const float4*)Wh);
    hprep_kernel<<<(Bsz * 128) / 256, 256>>>((const float4*)h0);
    bprep_kernel<<<(5 * G4) / 256, 256>>>(b0, bb, Wx0);

    dim3 grid(G4 / BN, Bsz / BM);   // 32 x 64 = 2048 CTAs
    for (int l = 0; l < 4; l++)
        lstm_layer_kernel<<<grid, NTH, SMEM_TOTAL>>>(l, x, c0, out);

    head_kernel<<<Bsz / 8, 256>>>(out + (size_t)Bsz * Hdim, Wd, bd,
                                  out + 2ull * (size_t)Bsz * Hdim);
}